// round 17
// baseline (speedup 1.0000x reference)
#include <cuda_runtime.h>

// DenseCRFLoss on GB300 — R11: single-resident-wave grid (576 blocks, 4/SM),
// scalar post-ex2 accumulation (no pack MOVs), QSPLIT=4, parallel prep.
//
// loss = -(1/N) * sum_{n,k,p,q} S[n,k,p] * exp(-0.5*||f_p - f_q||^2) * S[n,k,q]
// out  = WEIGHT * loss, WEIGHT = 2e-9, N = 4.
// K_pq = exp2( f'_p . f'_q + h'_p + h'_q ).  Symmetry: diag + 2*strict-upper.
// s0+s1=1: w = a_p*s0q + b_p -> split accumulators, a/b applied in epilogue.

#define N_IMG   4
#define P       4096
#define TS      512             // tile side
#define NT      8               // P / TS
#define NTRI    36              // upper-tri tiles
#define QSPLIT  4               // q-chunks per tile
#define QC      (TS / QSPLIT)   // 128 q's per block
#define NBLOCKS (N_IMG * NTRI * QSPLIT)  // 576  (<= 148*4: one resident wave)
#define THREADS 256
#define TP      2               // p's per thread

typedef unsigned long long u64;

__device__ u64   g_qrec[N_IMG * (P / 2) * 8];   // packed q-pair records, 64B each
__device__ float g_pfeat[N_IMG * P * 8];        // per-pixel [f0..f4, h, a, b]
__device__ float g_partial[NBLOCKS];
__device__ unsigned int g_count;                // zero-init; reset each run

__device__ __forceinline__ float ex2f(float x) {
    float r; asm("ex2.approx.f32 %0, %1;" : "=f"(r) : "f"(x)); return r;
}
__device__ __forceinline__ u64 fma2(u64 a, u64 b, u64 c) {
    u64 d; asm("fma.rn.f32x2 %0, %1, %2, %3;" : "=l"(d) : "l"(a), "l"(b), "l"(c)); return d;
}
__device__ __forceinline__ u64 add2(u64 a, u64 b) {
    u64 d; asm("add.rn.f32x2 %0, %1, %2;" : "=l"(d) : "l"(a), "l"(b)); return d;
}
__device__ __forceinline__ u64 pack2(float lo, float hi) {
    u64 d; asm("mov.b64 %0, {%1, %2};" : "=l"(d) : "f"(lo), "f"(hi)); return d;
}
__device__ __forceinline__ float2 unpack2(u64 v) {
    float2 r; asm("mov.b64 {%0, %1}, %2;" : "=f"(r.x), "=f"(r.y) : "l"(v)); return r;
}

// Feature for pixel pix of image n: f[0..4] scaled features, f[5]=h', f[6]=s0.
__device__ __forceinline__ void feat(const float* __restrict__ img,
                                     const float* __restrict__ seg,
                                     int n, int pix, float f[7]) {
    const float LOG2E = 1.44269504088896340736f;
    const float SQ    = 1.20112240878644981f;   // sqrt(LOG2E)
    int y = pix >> 6, x = pix & 63;
    int o = (2 * y) * 128 + 2 * x;

    const float* ib = img + (size_t)n * 3 * 16384;
    float r = ib[o];
    float g = ib[16384 + o];
    float b = ib[32768 + o];

    float f0 = (float)x * (1.0f / 50.0f);   // SIGMA_XY * SCALE = 50
    float f1 = (float)y * (1.0f / 50.0f);
    float f2 = r * (1.0f / 15.0f);          // SIGMA_RGB = 15
    float f3 = g * (1.0f / 15.0f);
    float f4 = b * (1.0f / 15.0f);
    float h = -0.5f * LOG2E * (f0*f0 + f1*f1 + f2*f2 + f3*f3 + f4*f4);

    const float* sb = seg + (size_t)n * 2 * 16384;
    float s0 = 0.25f * (sb[o] + sb[o+1] + sb[o+128] + sb[o+129]);

    f[0] = f0 * SQ; f[1] = f1 * SQ; f[2] = f2 * SQ; f[3] = f3 * SQ; f[4] = f4 * SQ;
    f[5] = h;       f[6] = s0;
}

// ---------------------------------------------------------------------------
// Prep: one thread per PIXEL (16384 threads, 128 blocks). Writes its p-record
// (2x STG.128) and its half of the packed q-pair record (7x STG.32).
// ---------------------------------------------------------------------------
__global__ void __launch_bounds__(128)
crf_prep(const float* __restrict__ img, const float* __restrict__ seg) {
    int idx = blockIdx.x * blockDim.x + threadIdx.x;
    if (idx >= N_IMG * P) return;
    int n = idx >> 12;
    int pix = idx & (P - 1);

    float f[7];
    feat(img, seg, n, pix, f);

    float4* pr = reinterpret_cast<float4*>(&g_pfeat[(size_t)idx * 8]);
    pr[0] = make_float4(f[0], f[1], f[2], f[3]);
    pr[1] = make_float4(f[4], f[5], 2.0f * f[6] - 1.0f, 1.0f - f[6]);

    // q-pair record: component c of pixel-pair rec at float offset rec*16 + c*2 + half
    int rec = idx >> 1, half = idx & 1;
    float* q = reinterpret_cast<float*>(g_qrec) + (size_t)rec * 16 + half;
    #pragma unroll
    for (int c = 0; c < 7; c++) q[c * 2] = f[c];
}

// ---------------------------------------------------------------------------
// Main: block = (image n, tri-tile (i,j), q-chunk qc). p-tile (512) in regs
// (TP=2 broadcast-packed), q-chunk (64 records = 4KB) in smem.
// Exponent chain packed f32x2; post-ex2 accumulation scalar (no pack MOVs).
// ---------------------------------------------------------------------------
__global__ void __launch_bounds__(THREADS, 4)
crf_main(float* __restrict__ out) {
    __shared__ u64 sq[(QC / 2) * 8];   // 64 records x 64B = 4KB

    int blk = blockIdx.x;
    int qc = blk & (QSPLIT - 1);
    int t  = (blk >> 2) % NTRI;
    int n  = blk / (NTRI * QSPLIT);
    int i = 0;
    {
        int rem = t;
        while (rem >= NT - i) { rem -= NT - i; i++; }
        t = i + rem;   // j
    }
    int j = t;
    int tid = threadIdx.x;

    // q-chunk copy: 512 u64, two per thread.
    {
        const u64* src = &g_qrec[(size_t)(n * (P / 2) + j * (TS / 2) + qc * (QC / 2)) * 8];
        sq[tid]           = src[tid];
        sq[tid + THREADS] = src[tid + THREADS];
    }

    // p records -> broadcast-packed registers.
    u64 px[TP][5], hp[TP];
    float ap[TP], bp[TP];
    float acc1A[TP], acc1B[TP], acc0A[TP], acc0B[TP];
    #pragma unroll
    for (int tp = 0; tp < TP; tp++) {
        const float4* pf = reinterpret_cast<const float4*>(
            &g_pfeat[(size_t)(n * P + i * TS + tid + tp * THREADS) * 8]);
        float4 v0 = pf[0];
        float4 v1 = pf[1];
        px[tp][0] = pack2(v0.x, v0.x);
        px[tp][1] = pack2(v0.y, v0.y);
        px[tp][2] = pack2(v0.z, v0.z);
        px[tp][3] = pack2(v0.w, v0.w);
        px[tp][4] = pack2(v1.x, v1.x);
        hp[tp]    = pack2(v1.y, v1.y);
        ap[tp] = v1.z;
        bp[tp] = v1.w;
        acc1A[tp] = 0.0f; acc1B[tp] = 0.0f;
        acc0A[tp] = 0.0f; acc0B[tp] = 0.0f;
    }
    __syncthreads();

    #pragma unroll 8
    for (int jq = 0; jq < QC / 2; jq++) {
        const ulonglong2* qd = reinterpret_cast<const ulonglong2*>(&sq[jq * 8]);
        ulonglong2 A = qd[0];   // {f0 pair, f1 pair}
        ulonglong2 B = qd[1];   // {f2 pair, f3 pair}
        ulonglong2 C = qd[2];   // {f4 pair, h  pair}
        float2 s0 = *reinterpret_cast<const float2*>(&sq[jq * 8 + 6]);  // s0A, s0B
        #pragma unroll
        for (int tp = 0; tp < TP; tp++) {
            u64 L = add2(hp[tp], C.y);
            L = fma2(px[tp][0], A.x, L);
            L = fma2(px[tp][1], A.y, L);
            L = fma2(px[tp][2], B.x, L);
            L = fma2(px[tp][3], B.y, L);
            L = fma2(px[tp][4], C.x, L);
            float2 Lf = unpack2(L);
            float kA = ex2f(Lf.x);
            float kB = ex2f(Lf.y);
            acc1A[tp] = fmaf(kA, s0.x, acc1A[tp]);
            acc1B[tp] = fmaf(kB, s0.y, acc1B[tp]);
            acc0A[tp] += kA;
            acc0B[tp] += kB;
        }
    }

    float a = 0.0f;
    #pragma unroll
    for (int tp = 0; tp < TP; tp++)
        a += ap[tp] * (acc1A[tp] + acc1B[tp]) + bp[tp] * (acc0A[tp] + acc0B[tp]);
    if (i != j) a *= 2.0f;   // symmetry weight

    // Deterministic block reduction.
    __shared__ float red[THREADS / 32];
    #pragma unroll
    for (int o = 16; o; o >>= 1) a += __shfl_down_sync(0xffffffffu, a, o);
    if ((tid & 31) == 0) red[tid >> 5] = a;
    __syncthreads();
    __shared__ bool is_last;
    if (tid == 0) {
        float v = 0.0f;
        #pragma unroll
        for (int w = 0; w < THREADS / 32; w++) v += red[w];
        g_partial[blk] = v;
        __threadfence();
        unsigned int c = atomicAdd(&g_count, 1u);
        is_last = (c == NBLOCKS - 1);
    }
    __syncthreads();

    // Last block: deterministic fixed-order final reduction + counter reset.
    if (is_last) {
        __threadfence();
        if (tid < 32) {
            float v = 0.0f;
            for (int k = tid; k < NBLOCKS; k += 32) v += g_partial[k];
            #pragma unroll
            for (int o = 16; o; o >>= 1) v += __shfl_down_sync(0xffffffffu, v, o);
            if (tid == 0) {
                out[0] = -(2e-9f / (float)N_IMG) * v;   // WEIGHT * (-sum / N)
                g_count = 0;                             // reset for next replay
            }
        }
    }
}

extern "C" void kernel_launch(void* const* d_in, const int* in_sizes, int n_in,
                              void* d_out, int out_size) {
    const float* images = (const float*)d_in[0];
    const float* segs   = (const float*)d_in[1];
    float* out = (float*)d_out;

    crf_prep<<<(N_IMG * P + 127) / 128, 128>>>(images, segs);
    crf_main<<<NBLOCKS, THREADS>>>(out);
}